// round 2
// baseline (speedup 1.0000x reference)
#include <cuda_runtime.h>
#include <cstdint>

#define BATCH 4
#define NN 1024
#define LL 64
#define NP 256
#define IMG_PIX (BATCH * NN * NN)          // 4,194,304

// ---------------- scratch (device globals; no allocation) ----------------
__device__ float2 g_X[BATCH * NN * NN];            // spectrum of x (unshifted)
__device__ float2 g_S1[BATCH * LL * NP * NP];      // patch scratch; reused as D
__device__ float  g_ACC[BATCH * NN * NN * 2];      // scatter accumulator (re,im)

// ---------------- complex helpers ----------------
__device__ __forceinline__ float2 cadd(float2 a, float2 b){ return make_float2(a.x+b.x, a.y+b.y); }
__device__ __forceinline__ float2 csub(float2 a, float2 b){ return make_float2(a.x-b.x, a.y-b.y); }
__device__ __forceinline__ float2 cmul(float2 a, float2 b){
    return make_float2(fmaf(a.x, b.x, -a.y*b.y), fmaf(a.x, b.y, a.y*b.x));
}

// ---------------- zero accumulator ----------------
__global__ void k_zero_acc() {
    int i = blockIdx.x * blockDim.x + threadIdx.x;
    float4* p = (float4*)g_ACC;
    const int n = BATCH * NN * NN * 2 / 4;
    if (i < n) p[i] = make_float4(0.f, 0.f, 0.f, 0.f);
}

// ---------------- shared-mem Stockham (autosort, natural in/out) ----------------
// N=1024, 512 threads, ping-pong buffers. Returns buffer holding result.
__device__ __forceinline__ float2* stockham1024(float2* b0, float2* b1, const float2* tw, int tid) {
    float2 *src = b0, *dst = b1;
    #pragma unroll
    for (int stage = 0; stage < 10; ++stage) {
        int s   = 1 << stage;
        int off = tid & ~(s - 1);
        float2 a = src[tid];
        float2 b = src[tid + 512];
        float2 w = tw[off];
        dst[tid + off]     = cadd(a, b);
        dst[tid + off + s] = cmul(csub(a, b), w);
        __syncthreads();
        float2* t = src; src = dst; dst = t;
    }
    return src;   // 10 stages (even) -> b0
}

// N=256, 128 threads per row (lt = local tid)
__device__ __forceinline__ float2* stockham256(float2* b0, float2* b1, const float2* tw, int lt) {
    float2 *src = b0, *dst = b1;
    #pragma unroll
    for (int stage = 0; stage < 8; ++stage) {
        int s   = 1 << stage;
        int off = lt & ~(s - 1);
        float2 a = src[lt];
        float2 b = src[lt + 128];
        float2 w = tw[off];
        dst[lt + off]     = cadd(a, b);
        dst[lt + off + s] = cmul(csub(a, b), w);
        __syncthreads();
        float2* t = src; src = dst; dst = t;
    }
    return src;   // 8 stages (even) -> b0
}

// ---------------- K1: forward row FFT 1024 of planar complex input -> g_X ----------------
__global__ void k_rows_fwd_planar(const float* __restrict__ re, const float* __restrict__ im) {
    __shared__ float2 buf0[NN];
    __shared__ float2 buf1[NN];
    __shared__ float2 tw[NN/2];
    int row = blockIdx.x;            // [0, B*NN)
    int tid = threadIdx.x;           // 512
    {
        float x = -2.0f * (float)tid / (float)NN;   // exact
        float s, c; sincospif(x, &s, &c);
        tw[tid] = make_float2(c, s);
    }
    const float* rp = re + (size_t)row * NN;
    const float* ip = im + (size_t)row * NN;
    buf0[tid]       = make_float2(rp[tid],       ip[tid]);
    buf0[tid + 512] = make_float2(rp[tid + 512], ip[tid + 512]);
    __syncthreads();
    float2* res = stockham1024(buf0, buf1, tw, tid);
    float2* o = g_X + (size_t)row * NN;
    o[tid]       = res[tid];
    o[tid + 512] = res[tid + 512];
}

// ---------------- K5: inverse (unnormalized) row FFT 1024 of ACC -> g_S1 (as D) ----------------
__global__ void k_rows_inv_acc() {
    __shared__ float2 buf0[NN];
    __shared__ float2 buf1[NN];
    __shared__ float2 tw[NN/2];
    int row = blockIdx.x;
    int tid = threadIdx.x;
    {
        float x = 2.0f * (float)tid / (float)NN;
        float s, c; sincospif(x, &s, &c);
        tw[tid] = make_float2(c, s);
    }
    const float2* src = ((const float2*)g_ACC) + (size_t)row * NN;
    buf0[tid]       = src[tid];
    buf0[tid + 512] = src[tid + 512];
    __syncthreads();
    float2* res = stockham1024(buf0, buf1, tw, tid);
    float2* o = g_S1 + (size_t)row * NN;
    o[tid]       = res[tid];
    o[tid + 512] = res[tid + 512];
}

// ---------------- column FFT 1024: 16 columns per block, in-place DIT w/ bitrev load ----------------
#define CCOLS 16
#define CSTR  17
#define COL_SMEM_BYTES ((NN * CSTR + NN/2) * (int)sizeof(float2))   // 143,360

__global__ void k_cols_fwd_X() {
    extern __shared__ float2 smem[];
    float2* sm = smem;
    float2* tw = smem + NN * CSTR;
    int b  = blockIdx.x >> 6;
    int c0 = (blockIdx.x & 63) * CCOLS;
    int tid = threadIdx.x;   // 512
    {
        float x = -2.0f * (float)tid / (float)NN;
        float s, c; sincospif(x, &s, &c);
        tw[tid] = make_float2(c, s);
    }
    float2* img = g_X + (size_t)b * NN * NN;
    int c = tid & 15, r0 = tid >> 4;     // 32 row-groups
    for (int it = 0; it < 32; ++it) {
        int r  = r0 + (it << 5);
        int br = __brev((unsigned)r) >> 22;   // 10-bit reversal
        sm[br * CSTR + c] = img[(size_t)r * NN + c0 + c];
    }
    __syncthreads();
    #pragma unroll
    for (int ll = 1; ll <= 10; ++ll) {
        int half = 1 << (ll - 1);
        #pragma unroll
        for (int u = 0; u < 16; ++u) {
            int t  = tid + (u << 9);
            int cc = t & 15;
            int bf = t >> 4;
            int k    = bf & (half - 1);
            int base = ((bf >> (ll - 1)) << ll) | k;
            float2 w = tw[k << (10 - ll)];
            float2 a = sm[base * CSTR + cc];
            float2 v = cmul(sm[(base + half) * CSTR + cc], w);
            sm[base * CSTR + cc]          = cadd(a, v);
            sm[(base + half) * CSTR + cc] = csub(a, v);
        }
        __syncthreads();
    }
    for (int it = 0; it < 32; ++it) {
        int r = r0 + (it << 5);
        img[(size_t)r * NN + c0 + c] = sm[r * CSTR + c];
    }
}

// ---------------- K6: inverse col FFT 1024 of D (=g_S1) + fused final combine -> out ----------------
__global__ void k_cols_inv_final(const float* __restrict__ img_a, const float* __restrict__ xre,
                                 const float* __restrict__ xim,  const float* __restrict__ lamb,
                                 const float* __restrict__ eta1, float* __restrict__ out,
                                 long long out_size) {
    extern __shared__ float2 smem[];
    float2* sm = smem;
    float2* tw = smem + NN * CSTR;
    int b  = blockIdx.x >> 6;
    int c0 = (blockIdx.x & 63) * CCOLS;
    int tid = threadIdx.x;
    {
        float x = 2.0f * (float)tid / (float)NN;
        float s, c; sincospif(x, &s, &c);
        tw[tid] = make_float2(c, s);
    }
    const float2* img = g_S1 + (size_t)b * NN * NN;
    int c = tid & 15, r0 = tid >> 4;
    for (int it = 0; it < 32; ++it) {
        int r  = r0 + (it << 5);
        int br = __brev((unsigned)r) >> 22;
        sm[br * CSTR + c] = img[(size_t)r * NN + c0 + c];
    }
    __syncthreads();
    #pragma unroll
    for (int ll = 1; ll <= 10; ++ll) {
        int half = 1 << (ll - 1);
        #pragma unroll
        for (int u = 0; u < 16; ++u) {
            int t  = tid + (u << 9);
            int cc = t & 15;
            int bf = t >> 4;
            int k    = bf & (half - 1);
            int base = ((bf >> (ll - 1)) << ll) | k;
            float2 w = tw[k << (10 - ll)];
            float2 a = sm[base * CSTR + cc];
            float2 v = cmul(sm[(base + half) * CSTR + cc], w);
            sm[base * CSTR + cc]          = cadd(a, v);
            sm[(base + half) * CSTR + cc] = csub(a, v);
        }
        __syncthreads();
    }
    float e1  = eta1[0];
    float lm  = lamb[0];
    float bco = 100.0f * e1 * lm;                  // coeff on temp_x term / z_f term
    float aco = 10.0f  * e1;
    float coef = aco / ((float)LL * 1048576.0f);   // a / (L * N^2): ifft2 norm + /L
    float one_m_b = 1.0f - bco;
    for (int it = 0; it < 32; ++it) {
        int r = r0 + (it << 5);
        long long idx = ((long long)b * NN + r) * NN + c0 + c;
        float2 d = sm[r * CSTR + c];
        float xr = xre[idx], xi = xim[idx];
        float m  = sqrtf(fmaf(xr, xr, xi * xi)) + 1e-6f;
        float fa = bco * img_a[idx] / m;
        float rcx = one_m_b * xr - coef * d.x + fa * xr;
        float rcy = one_m_b * xi - coef * d.y + fa * xi;
        if (idx < out_size) out[idx] = sqrtf(fmaf(rcx, rcx, rcy * rcy));
        // planar complex output: [im_ra | Re(im_rc) | Im(im_rc)]
        long long ore = (long long)IMG_PIX + idx;
        long long oim = (long long)(2 * IMG_PIX) + idx;
        if (ore < out_size) out[ore] = rcx;
        if (oim < out_size) out[oim] = rcy;
    }
}

// ---------------- P1: patch gather * CTF + row IFFT 256 -> g_S1 ----------------
// block = 4 patch rows, 512 threads; grid = B*L*64
__global__ void k_p1(const int* __restrict__ masks, const float* __restrict__ ctf) {
    __shared__ float2 buf[4][2 * NP];
    __shared__ float2 tw[NP / 2];
    int tid  = threadIdx.x;
    int lrow = tid >> 7, lt = tid & 127;
    if (tid < 128) {
        float x = 2.0f * (float)tid / (float)NP;   // inverse sign
        float s, c; sincospif(x, &s, &c);
        tw[tid] = make_float2(c, s);
    }
    int blk = blockIdx.x;
    int rc4 = blk & 63;
    int pk  = blk >> 6;          // b*64 + k
    int b   = pk >> 6;
    int k   = pk & 63;
    int mr = masks[2 * k]     - 1;
    int mc = masks[2 * k + 1] - 1;
    int i  = (rc4 << 2) + lrow;                 // patch row
    int gr = (mr + i + 512) & 1023;             // fftshift folded into index
    const float2* Xrow = g_X + ((size_t)b * NN + gr) * NN;
    float2* b0 = buf[lrow];
    float2* b1 = b0 + NP;
    #pragma unroll
    for (int h = 0; h < 2; ++h) {
        int j  = lt + h * 128;
        int gc = (mc + j + 512) & 1023;
        float2 v = Xrow[gc];
        float cf = ctf[i * NP + j];
        b0[j] = make_float2(v.x * cf, v.y * cf);
    }
    __syncthreads();
    float2* res = stockham256(b0, b1, tw, lt);
    float2* o = g_S1 + ((size_t)pk * NP + i) * NP;
    o[lt]       = res[lt];
    o[lt + 128] = res[lt + 128];
}

// ---------------- P2: col IFFT 256 + magnitude projection + col FFT 256 (in place) ----------------
#define PSTR 17
__global__ void k_p2(const float* __restrict__ Y) {
    __shared__ float2 sm[NP * PSTR];    // 34,816 B
    __shared__ float2 tw[NP / 2];       // forward-sign table
    int tid = threadIdx.x;              // 512
    if (tid < 128) {
        float x = -2.0f * (float)tid / (float)NP;
        float s, c; sincospif(x, &s, &c);
        tw[tid] = make_float2(c, s);
    }
    int pk = blockIdx.x >> 4;
    int c0 = (blockIdx.x & 15) << 4;
    float2* P = g_S1 + (size_t)pk * NP * NP;
    int c = tid & 15, r0 = tid >> 4;    // 8 row-groups of 32
    for (int it = 0; it < 8; ++it) {
        int r  = r0 + (it << 5);
        int br = __brev((unsigned)r) >> 24;    // 8-bit reversal
        sm[br * PSTR + c] = P[r * NP + c0 + c];
    }
    __syncthreads();
    // inverse DIT (conjugated twiddles), natural-order output
    #pragma unroll
    for (int ll = 1; ll <= 8; ++ll) {
        int half = 1 << (ll - 1);
        #pragma unroll
        for (int u = 0; u < 4; ++u) {
            int t  = tid + (u << 9);
            int cc = t & 15;
            int bf = t >> 4;
            int k    = bf & (half - 1);
            int base = ((bf >> (ll - 1)) << ll) | k;
            float2 w = tw[k << (8 - ll)];
            w.y = -w.y;
            float2 a = sm[base * PSTR + cc];
            float2 v = cmul(sm[(base + half) * PSTR + cc], w);
            sm[base * PSTR + cc]          = cadd(a, v);
            sm[(base + half) * PSTR + cc] = csub(a, v);
        }
        __syncthreads();
    }
    // elementwise: Bz = w/65536 ; Cz = Bz - sqrt(Y)*Bz/|Bz|
    const float* Yp = Y + (size_t)pk * NP * NP;
    const float inv = 1.0f / 65536.0f;
    for (int it = 0; it < 8; ++it) {
        int r = r0 + (it << 5);
        float2 w = sm[r * PSTR + c];
        w.x *= inv; w.y *= inv;
        float mag = sqrtf(fmaf(w.x, w.x, w.y * w.y));
        float sy  = sqrtf(Yp[r * NP + c0 + c]);
        float2 res;
        if (mag > 0.0f) {
            float f = 1.0f - sy / mag;
            res = make_float2(w.x * f, w.y * f);
        } else {
            res = make_float2(-sy, 0.0f);
        }
        sm[r * PSTR + c] = res;
    }
    __syncthreads();
    // forward DIF, natural input -> bit-reversed output (store compensates)
    #pragma unroll
    for (int ll = 8; ll >= 1; --ll) {
        int half = 1 << (ll - 1);
        #pragma unroll
        for (int u = 0; u < 4; ++u) {
            int t  = tid + (u << 9);
            int cc = t & 15;
            int bf = t >> 4;
            int k    = bf & (half - 1);
            int base = ((bf >> (ll - 1)) << ll) | k;
            float2 w = tw[k << (8 - ll)];
            float2 a = sm[base * PSTR + cc];
            float2 v = sm[(base + half) * PSTR + cc];
            sm[base * PSTR + cc]          = cadd(a, v);
            sm[(base + half) * PSTR + cc] = cmul(csub(a, v), w);
        }
        __syncthreads();
    }
    for (int it = 0; it < 8; ++it) {
        int r  = r0 + (it << 5);
        int br = __brev((unsigned)r) >> 24;
        P[br * NP + c0 + c] = sm[r * PSTR + c];   // storage row br holds spectral row br
    }
}

// ---------------- P3: row FFT 256 * CTF + atomic scatter into ACC ----------------
__global__ void k_p3(const int* __restrict__ masks, const float* __restrict__ ctf) {
    __shared__ float2 buf[4][2 * NP];
    __shared__ float2 tw[NP / 2];
    int tid  = threadIdx.x;
    int lrow = tid >> 7, lt = tid & 127;
    if (tid < 128) {
        float x = -2.0f * (float)tid / (float)NP;  // forward
        float s, c; sincospif(x, &s, &c);
        tw[tid] = make_float2(c, s);
    }
    int blk = blockIdx.x;
    int rc4 = blk & 63;
    int pk  = blk >> 6;
    int b   = pk >> 6;
    int k   = pk & 63;
    int mr = masks[2 * k]     - 1;
    int mc = masks[2 * k + 1] - 1;
    int i  = (rc4 << 2) + lrow;
    const float2* src = g_S1 + ((size_t)pk * NP + i) * NP;
    float2* b0 = buf[lrow];
    float2* b1 = b0 + NP;
    b0[lt]       = src[lt];
    b0[lt + 128] = src[lt + 128];
    __syncthreads();
    float2* res = stockham256(b0, b1, tw, lt);
    int gr = (mr + i + 512) & 1023;
    float* accrow = g_ACC + ((size_t)b * NN + gr) * NN * 2;
    #pragma unroll
    for (int h = 0; h < 2; ++h) {
        int j  = lt + h * 128;
        float cf = ctf[i * NP + j];
        float2 v = res[j];
        int gc = (mc + j + 512) & 1023;
        atomicAdd(accrow + gc * 2,     v.x * cf);
        atomicAdd(accrow + gc * 2 + 1, v.y * cf);
    }
}

// ---------------- launch ----------------
extern "C" void kernel_launch(void* const* d_in, const int* in_sizes, int n_in,
                              void* d_out, int out_size) {
    const float* Img_a = (const float*)d_in[0];
    const float* Xre   = (const float*)d_in[1];
    const float* Xim   = (const float*)d_in[2];
    const float* Y     = (const float*)d_in[3];
    const int*   Masks = (const int*)  d_in[4];
    const float* CTF   = (const float*)d_in[5];
    const float* lamb  = (const float*)d_in[6];
    const float* eta1  = (const float*)d_in[7];
    float* out = (float*)d_out;

    cudaFuncSetAttribute((const void*)k_cols_fwd_X,
                         cudaFuncAttributeMaxDynamicSharedMemorySize, COL_SMEM_BYTES);
    cudaFuncSetAttribute((const void*)k_cols_inv_final,
                         cudaFuncAttributeMaxDynamicSharedMemorySize, COL_SMEM_BYTES);

    // 1. zero scatter accumulator
    k_zero_acc<<<4096, 512>>>();
    // 2. X = fft2(x): rows then cols (unshifted spectrum; shifts folded into indices)
    k_rows_fwd_planar<<<BATCH * NN, 512>>>(Xre, Xim);
    k_cols_fwd_X<<<BATCH * (NN / CCOLS), 512, COL_SMEM_BYTES>>>();
    // 3. patch pipeline
    k_p1<<<BATCH * LL * (NP / 4), 512>>>(Masks, CTF);
    k_p2<<<BATCH * LL * (NP / 16), 512>>>(Y);
    k_p3<<<BATCH * LL * (NP / 4), 512>>>(Masks, CTF);
    // 4. D = ifft2_raw(ACC): rows then cols + fused final combine & output
    k_rows_inv_acc<<<BATCH * NN, 512>>>();
    k_cols_inv_final<<<BATCH * (NN / CCOLS), 512, COL_SMEM_BYTES>>>(
        Img_a, Xre, Xim, lamb, eta1, out, (long long)out_size);
}

// round 4
// speedup vs baseline: 1.0375x; 1.0375x over previous
#include <cuda_runtime.h>
#include <cstdint>

#define BATCH 4
#define NN 1024
#define LL 64
#define NP 256
#define IMG_PIX (BATCH * NN * NN)

// ---------------- scratch ----------------
__device__ float2 g_X[BATCH * NN * NN];
__device__ float2 g_S1[BATCH * LL * NP * NP];
__device__ float  g_ACC[BATCH * NN * NN * 2];

// ---------------- complex helpers ----------------
__device__ __forceinline__ float2 cadd(float2 a, float2 b){ return make_float2(a.x+b.x, a.y+b.y); }
__device__ __forceinline__ float2 csub(float2 a, float2 b){ return make_float2(a.x-b.x, a.y-b.y); }
__device__ __forceinline__ float2 cmul(float2 a, float2 b){
    return make_float2(fmaf(a.x, b.x, -a.y*b.y), fmaf(a.x, b.y, a.y*b.x));
}
__device__ __forceinline__ float2 rotn(float2 a){ return make_float2(a.y, -a.x); }  // *(-i)
__device__ __forceinline__ float2 rotp(float2 a){ return make_float2(-a.y, a.x); }  // *(+i)

// base-4 digit reversals
__device__ __forceinline__ int dr8 (int r){ int x = __brev((unsigned)r) >> 24; return ((x & 0x55) << 1) | ((x & 0xAA) >> 1); }
__device__ __forceinline__ int dr10(int r){ int x = __brev((unsigned)r) >> 22; return ((x & 0x155) << 1) | ((x & 0x2AA) >> 1); }

// ---------------- zero accumulator ----------------
__global__ void k_zero_acc() {
    int i = blockIdx.x * blockDim.x + threadIdx.x;
    float4* p = (float4*)g_ACC;
    const int n = BATCH * NN * NN * 2 / 4;
    if (i < n) p[i] = make_float4(0.f, 0.f, 0.f, 0.f);
}

// ---------------- Stockham radix-4 (N pts, N/4 threads, NST stages) ----------------
// Twiddles w^{off}, w^{2off} with off=(j div s)*s apply at EVERY stage incl. s=1.
template<int N, int NST, bool INV>
__device__ __forceinline__ float2* stockham_r4(float2* b0, float2* b1, const float2* tw, int j) {
    float2 *src = b0, *dst = b1;
    int s = 1;
    #pragma unroll
    for (int st = 0; st < NST; ++st) {
        int off = j & ~(s - 1);
        float2 x0 = src[j], x1 = src[j + N/4], x2 = src[j + N/2], x3 = src[j + 3*(N/4)];
        float2 w1 = tw[off], w2 = tw[2*off];
        float2 t0 = cadd(x0, x2), t1 = cmul(csub(x0, x2), w1);
        float2 t2 = cadd(x1, x3);
        float2 t3 = cmul(csub(x1, x3), w1);
        t3 = INV ? rotp(t3) : rotn(t3);
        float2 y0 = cadd(t0, t2), y1 = cadd(t1, t3);
        float2 y2 = cmul(csub(t0, t2), w2), y3 = cmul(csub(t1, t3), w2);
        if (st == 0) {
            // base = 4j: contiguous, vectorize
            float4* d4 = (float4*)(dst + 4*j);
            d4[0] = make_float4(y0.x, y0.y, y1.x, y1.y);
            d4[1] = make_float4(y2.x, y2.y, y3.x, y3.y);
        } else {
            int base = j + 3*off;
            dst[base]       = y0;
            dst[base + s]   = y1;
            dst[base + 2*s] = y2;
            dst[base + 3*s] = y3;
        }
        __syncthreads();
        float2* t = src; src = dst; dst = t;
        s <<= 2;
    }
    return src;
}

// ---------------- K1: forward row FFT1024 of planar input -> g_X (2 rows/block) ----------------
__global__ void k_rows_fwd_planar(const float* __restrict__ re, const float* __restrict__ im) {
    __shared__ __align__(16) float2 buf[2][2][NN];
    __shared__ float2 tw[NN/2];
    int tid = threadIdx.x;                  // 512
    int lrow = tid >> 8, j = tid & 255;
    #pragma unroll
    for (int h = 0; h < 2; ++h) {
        int i = tid + h * 512;
        float x = -2.0f * (float)i / (float)NN;
        float s, c; sincospif(x, &s, &c);
        if (i < NN/2) tw[i] = make_float2(c, s);
    }
    int row = blockIdx.x * 2 + lrow;
    const float* rp = re + (size_t)row * NN;
    const float* ip = im + (size_t)row * NN;
    float2* b0 = buf[lrow][0];
    float2* b1 = buf[lrow][1];
    #pragma unroll
    for (int h = 0; h < 4; ++h) b0[j + h*256] = make_float2(rp[j + h*256], ip[j + h*256]);
    __syncthreads();
    float2* res = stockham_r4<NN, 5, false>(b0, b1, tw, j);
    float2* o = g_X + (size_t)row * NN;
    #pragma unroll
    for (int h = 0; h < 4; ++h) o[j + h*256] = res[j + h*256];
}

// ---------------- K5: inverse row FFT1024 of ACC -> g_S1 ----------------
__global__ void k_rows_inv_acc() {
    __shared__ __align__(16) float2 buf[2][2][NN];
    __shared__ float2 tw[NN/2];
    int tid = threadIdx.x;
    int lrow = tid >> 8, j = tid & 255;
    #pragma unroll
    for (int h = 0; h < 2; ++h) {
        int i = tid + h * 512;
        float x = 2.0f * (float)i / (float)NN;
        float s, c; sincospif(x, &s, &c);
        if (i < NN/2) tw[i] = make_float2(c, s);
    }
    int row = blockIdx.x * 2 + lrow;
    const float2* src = ((const float2*)g_ACC) + (size_t)row * NN;
    float2* b0 = buf[lrow][0];
    float2* b1 = buf[lrow][1];
    #pragma unroll
    for (int h = 0; h < 4; ++h) b0[j + h*256] = src[j + h*256];
    __syncthreads();
    float2* res = stockham_r4<NN, 5, true>(b0, b1, tw, j);
    float2* o = g_S1 + (size_t)row * NN;
    #pragma unroll
    for (int h = 0; h < 4; ++h) o[j + h*256] = res[j + h*256];
}

// ---------------- in-place radix-4 DIT, 1024 pts x 8 cols (digit-reversed input) ----------------
#define CCOLS 8
#define CSTR  9
#define COL_SMEM_BYTES ((NN * CSTR + NN/2) * (int)sizeof(float2))   // 77,824

template<bool INV>
__device__ __forceinline__ void dit1024_ip(float2* sm, const float2* tw, int tid) {
    #pragma unroll
    for (int lg = 1; lg <= 5; ++lg) {
        const int m = 1 << (2*lg), q = m >> 2;
        #pragma unroll
        for (int u = 0; u < 4; ++u) {
            int t   = tid + (u << 9);
            int cc  = t & 7;
            int idx = t >> 3;                    // 0..255
            int k   = idx & (q - 1);
            int g   = idx >> (2*lg - 2);
            int rb  = (g << (2*lg)) + k;
            int e   = k << (10 - 2*lg);
            float2 w1 = tw[e], w2 = tw[2*e];
            float2 w3 = cmul(w1, w2);
            float2 X0 = sm[rb*CSTR + cc];
            float2 X1 = cmul(sm[(rb+q)*CSTR + cc],   w1);
            float2 X2 = cmul(sm[(rb+2*q)*CSTR + cc], w2);
            float2 X3 = cmul(sm[(rb+3*q)*CSTR + cc], w3);
            float2 s  = cadd(X0, X2), d = csub(X0, X2);
            float2 s2 = cadd(X1, X3);
            float2 dd = csub(X1, X3);
            float2 d2 = INV ? rotp(dd) : rotn(dd);
            sm[rb*CSTR + cc]        = cadd(s, s2);
            sm[(rb+q)*CSTR + cc]    = cadd(d, d2);
            sm[(rb+2*q)*CSTR + cc]  = csub(s, s2);
            sm[(rb+3*q)*CSTR + cc]  = csub(d, d2);
        }
        __syncthreads();
    }
}

__global__ void k_cols_fwd_X() {
    extern __shared__ float2 smem[];
    float2* sm = smem;
    float2* tw = smem + NN * CSTR;
    int b  = blockIdx.x >> 7;
    int c0 = (blockIdx.x & 127) * CCOLS;
    int tid = threadIdx.x;   // 512
    {
        float x = -2.0f * (float)tid / (float)NN;
        float s, c; sincospif(x, &s, &c);
        tw[tid] = make_float2(c, s);
    }
    float2* img = g_X + (size_t)b * NN * NN;
    int c = tid & 7, r0 = tid >> 3;             // 64 row-groups
    for (int it = 0; it < 16; ++it) {
        int r = r0 + (it << 6);
        sm[dr10(r) * CSTR + c] = img[(size_t)r * NN + c0 + c];
    }
    __syncthreads();
    dit1024_ip<false>(sm, tw, tid);
    for (int it = 0; it < 16; ++it) {
        int r = r0 + (it << 6);
        img[(size_t)r * NN + c0 + c] = sm[r * CSTR + c];
    }
}

__global__ void k_cols_inv_final(const float* __restrict__ img_a, const float* __restrict__ xre,
                                 const float* __restrict__ xim,  const float* __restrict__ lamb,
                                 const float* __restrict__ eta1, float* __restrict__ out,
                                 long long out_size) {
    extern __shared__ float2 smem[];
    float2* sm = smem;
    float2* tw = smem + NN * CSTR;
    int b  = blockIdx.x >> 7;
    int c0 = (blockIdx.x & 127) * CCOLS;
    int tid = threadIdx.x;
    {
        float x = 2.0f * (float)tid / (float)NN;
        float s, c; sincospif(x, &s, &c);
        tw[tid] = make_float2(c, s);
    }
    const float2* img = g_S1 + (size_t)b * NN * NN;
    int c = tid & 7, r0 = tid >> 3;
    for (int it = 0; it < 16; ++it) {
        int r = r0 + (it << 6);
        sm[dr10(r) * CSTR + c] = img[(size_t)r * NN + c0 + c];
    }
    __syncthreads();
    dit1024_ip<true>(sm, tw, tid);
    float e1  = eta1[0];
    float lm  = lamb[0];
    float bco = 100.0f * e1 * lm;
    float aco = 10.0f  * e1;
    float coef = aco / ((float)LL * 1048576.0f);
    float one_m_b = 1.0f - bco;
    for (int it = 0; it < 16; ++it) {
        int r = r0 + (it << 6);
        long long idx = ((long long)b * NN + r) * NN + c0 + c;
        float2 d = sm[r * CSTR + c];
        float xr = xre[idx], xi = xim[idx];
        float m  = sqrtf(fmaf(xr, xr, xi * xi)) + 1e-6f;
        float fa = bco * img_a[idx] / m;
        float rcx = one_m_b * xr - coef * d.x + fa * xr;
        float rcy = one_m_b * xi - coef * d.y + fa * xi;
        if (idx < out_size) out[idx] = sqrtf(fmaf(rcx, rcx, rcy * rcy));
        long long ore = (long long)IMG_PIX + idx;
        long long oim = (long long)(2 * IMG_PIX) + idx;
        if (ore < out_size) out[ore] = rcx;
        if (oim < out_size) out[oim] = rcy;
    }
}

// ---------------- P1: patch gather * CTF + row IFFT256 -> g_S1 (8 rows/block) ----------------
__global__ void k_p1(const int* __restrict__ masks, const float* __restrict__ ctf) {
    __shared__ __align__(16) float2 buf[8][2][NP];
    __shared__ float2 tw[NP/2];
    int tid  = threadIdx.x;                  // 512
    int lrow = tid >> 6, lt = tid & 63;
    if (tid < 128) {
        float x = 2.0f * (float)tid / (float)NP;     // inverse sign
        float s, c; sincospif(x, &s, &c);
        tw[tid] = make_float2(c, s);
    }
    int blk = blockIdx.x;
    int rg  = blk & 31;
    int pk  = blk >> 5;
    int b   = pk >> 6;
    int k   = pk & 63;
    int mr = masks[2*k]     - 1;
    int mc = masks[2*k + 1] - 1;
    int i  = (rg << 3) + lrow;
    int gr = (mr + i + 512) & 1023;
    const float2* Xrow = g_X + ((size_t)b * NN + gr) * NN;
    float2* b0 = buf[lrow][0];
    float2* b1 = buf[lrow][1];
    #pragma unroll
    for (int h = 0; h < 4; ++h) {
        int j  = lt + h * 64;
        int gc = (mc + j + 512) & 1023;
        float2 v = Xrow[gc];
        float cf = ctf[i * NP + j];
        b0[j] = make_float2(v.x * cf, v.y * cf);
    }
    __syncthreads();
    float2* res = stockham_r4<NP, 4, true>(b0, b1, tw, lt);
    float2* o = g_S1 + ((size_t)pk * NP + i) * NP;
    #pragma unroll
    for (int h = 0; h < 4; ++h) o[lt + h*64] = res[lt + h*64];
}

// ---------------- P2: col IFFT256 + projection + col FFT256 (in place, radix-4) ----------------
#define PSTR 17
__global__ void k_p2(const float* __restrict__ Y) {
    __shared__ float2 sm[NP * PSTR];
    __shared__ float2 tw[NP/2];                // forward sign
    int tid = threadIdx.x;                     // 512
    if (tid < 128) {
        float x = -2.0f * (float)tid / (float)NP;
        float s, c; sincospif(x, &s, &c);
        tw[tid] = make_float2(c, s);
    }
    int pk = blockIdx.x >> 4;
    int c0 = (blockIdx.x & 15) << 4;
    float2* P = g_S1 + (size_t)pk * NP * NP;
    int c = tid & 15, r0 = tid >> 4;           // 32 row-groups
    for (int it = 0; it < 8; ++it) {
        int r = r0 + (it << 5);
        sm[dr8(r) * PSTR + c] = P[r * NP + c0 + c];
    }
    __syncthreads();
    // inverse radix-4 DIT (conjugate twiddles)
    #pragma unroll
    for (int lg = 1; lg <= 4; ++lg) {
        const int m = 1 << (2*lg), q = m >> 2;
        #pragma unroll
        for (int u = 0; u < 2; ++u) {
            int t   = tid + (u << 9);
            int cc  = t & 15;
            int idx = t >> 4;                  // 0..63
            int k   = idx & (q - 1);
            int g   = idx >> (2*lg - 2);
            int rb  = (g << (2*lg)) + k;
            int e   = k << (8 - 2*lg);
            float2 w1 = tw[e];   w1.y = -w1.y;
            float2 w2 = tw[2*e]; w2.y = -w2.y;
            float2 w3 = cmul(w1, w2);
            float2 X0 = sm[rb*PSTR + cc];
            float2 X1 = cmul(sm[(rb+q)*PSTR + cc],   w1);
            float2 X2 = cmul(sm[(rb+2*q)*PSTR + cc], w2);
            float2 X3 = cmul(sm[(rb+3*q)*PSTR + cc], w3);
            float2 s  = cadd(X0, X2), d = csub(X0, X2);
            float2 s2 = cadd(X1, X3);
            float2 d2 = rotp(csub(X1, X3));
            sm[rb*PSTR + cc]        = cadd(s, s2);
            sm[(rb+q)*PSTR + cc]    = cadd(d, d2);
            sm[(rb+2*q)*PSTR + cc]  = csub(s, s2);
            sm[(rb+3*q)*PSTR + cc]  = csub(d, d2);
        }
        __syncthreads();
    }
    // elementwise: Bz = w/65536 ; Cz = Bz - sqrt(Y)*Bz/|Bz|
    const float* Yp = Y + (size_t)pk * NP * NP;
    const float inv = 1.0f / 65536.0f;
    for (int it = 0; it < 8; ++it) {
        int r = r0 + (it << 5);
        float2 w = sm[r * PSTR + c];
        w.x *= inv; w.y *= inv;
        float mag = sqrtf(fmaf(w.x, w.x, w.y * w.y));
        float sy  = sqrtf(Yp[r * NP + c0 + c]);
        float2 res;
        if (mag > 0.0f) {
            float f = 1.0f - sy / mag;
            res = make_float2(w.x * f, w.y * f);
        } else {
            res = make_float2(-sy, 0.0f);
        }
        sm[r * PSTR + c] = res;
    }
    __syncthreads();
    // forward radix-4 DIF (natural input -> digit-reversed storage)
    #pragma unroll
    for (int lg = 4; lg >= 1; --lg) {
        const int m = 1 << (2*lg), q = m >> 2;
        #pragma unroll
        for (int u = 0; u < 2; ++u) {
            int t   = tid + (u << 9);
            int cc  = t & 15;
            int idx = t >> 4;
            int k   = idx & (q - 1);
            int g   = idx >> (2*lg - 2);
            int rb  = (g << (2*lg)) + k;
            int e   = k << (8 - 2*lg);
            float2 w1 = tw[e], w2 = tw[2*e];
            float2 w3 = cmul(w1, w2);
            float2 x0 = sm[rb*PSTR + cc];
            float2 x1 = sm[(rb+q)*PSTR + cc];
            float2 x2 = sm[(rb+2*q)*PSTR + cc];
            float2 x3 = sm[(rb+3*q)*PSTR + cc];
            float2 s02 = cadd(x0, x2), d02 = csub(x0, x2);
            float2 s13 = cadd(x1, x3);
            float2 ddr = rotn(csub(x1, x3));
            sm[rb*PSTR + cc]        = cadd(s02, s13);
            sm[(rb+q)*PSTR + cc]    = cmul(cadd(d02, ddr), w1);
            sm[(rb+2*q)*PSTR + cc]  = cmul(csub(s02, s13), w2);
            sm[(rb+3*q)*PSTR + cc]  = cmul(csub(d02, ddr), w3);
        }
        __syncthreads();
    }
    for (int it = 0; it < 8; ++it) {
        int r = r0 + (it << 5);
        P[r * NP + c0 + c] = sm[dr8(r) * PSTR + c];
    }
}

// ---------------- P3: row FFT256 * CTF + atomic scatter into ACC (8 rows/block) ----------------
__global__ void k_p3(const int* __restrict__ masks, const float* __restrict__ ctf) {
    __shared__ __align__(16) float2 buf[8][2][NP];
    __shared__ float2 tw[NP/2];
    int tid  = threadIdx.x;
    int lrow = tid >> 6, lt = tid & 63;
    if (tid < 128) {
        float x = -2.0f * (float)tid / (float)NP;    // forward
        float s, c; sincospif(x, &s, &c);
        tw[tid] = make_float2(c, s);
    }
    int blk = blockIdx.x;
    int rg  = blk & 31;
    int pk  = blk >> 5;
    int b   = pk >> 6;
    int k   = pk & 63;
    int mr = masks[2*k]     - 1;
    int mc = masks[2*k + 1] - 1;
    int i  = (rg << 3) + lrow;
    const float2* src = g_S1 + ((size_t)pk * NP + i) * NP;
    float2* b0 = buf[lrow][0];
    float2* b1 = buf[lrow][1];
    #pragma unroll
    for (int h = 0; h < 4; ++h) b0[lt + h*64] = src[lt + h*64];
    __syncthreads();
    float2* res = stockham_r4<NP, 4, false>(b0, b1, tw, lt);
    int gr = (mr + i + 512) & 1023;
    float* accrow = g_ACC + ((size_t)b * NN + gr) * NN * 2;
    #pragma unroll
    for (int h = 0; h < 4; ++h) {
        int j  = lt + h * 64;
        float cf = ctf[i * NP + j];
        float2 v = res[j];
        int gc = (mc + j + 512) & 1023;
        atomicAdd(accrow + gc * 2,     v.x * cf);
        atomicAdd(accrow + gc * 2 + 1, v.y * cf);
    }
}

// ---------------- launch ----------------
extern "C" void kernel_launch(void* const* d_in, const int* in_sizes, int n_in,
                              void* d_out, int out_size) {
    const float* Img_a = (const float*)d_in[0];
    const float* Xre   = (const float*)d_in[1];
    const float* Xim   = (const float*)d_in[2];
    const float* Y     = (const float*)d_in[3];
    const int*   Masks = (const int*)  d_in[4];
    const float* CTF   = (const float*)d_in[5];
    const float* lamb  = (const float*)d_in[6];
    const float* eta1  = (const float*)d_in[7];
    float* out = (float*)d_out;

    cudaFuncSetAttribute((const void*)k_cols_fwd_X,
                         cudaFuncAttributeMaxDynamicSharedMemorySize, COL_SMEM_BYTES);
    cudaFuncSetAttribute((const void*)k_cols_inv_final,
                         cudaFuncAttributeMaxDynamicSharedMemorySize, COL_SMEM_BYTES);

    k_zero_acc<<<4096, 512>>>();
    k_rows_fwd_planar<<<BATCH * NN / 2, 512>>>(Xre, Xim);
    k_cols_fwd_X<<<BATCH * (NN / CCOLS), 512, COL_SMEM_BYTES>>>();
    k_p1<<<BATCH * LL * (NP / 8), 512>>>(Masks, CTF);
    k_p2<<<BATCH * LL * (NP / 16), 512>>>(Y);
    k_p3<<<BATCH * LL * (NP / 8), 512>>>(Masks, CTF);
    k_rows_inv_acc<<<BATCH * NN / 2, 512>>>();
    k_cols_inv_final<<<BATCH * (NN / CCOLS), 512, COL_SMEM_BYTES>>>(
        Img_a, Xre, Xim, lamb, eta1, out, (long long)out_size);
}

// round 5
// speedup vs baseline: 1.9949x; 1.9228x over previous
#include <cuda_runtime.h>
#include <cstdint>

#define BATCH 4
#define NN 1024
#define LL 64
#define NP 256
#define IMG_PIX (BATCH * NN * NN)

// ---------------- scratch ----------------
__device__ float2 g_X[BATCH * NN * NN];
__device__ float2 g_S1[BATCH * LL * NP * NP];
__device__ float  g_ACC[BATCH * NN * NN * 2];

// ---------------- complex helpers ----------------
__device__ __forceinline__ float2 cadd(float2 a, float2 b){ return make_float2(a.x+b.x, a.y+b.y); }
__device__ __forceinline__ float2 csub(float2 a, float2 b){ return make_float2(a.x-b.x, a.y-b.y); }
__device__ __forceinline__ float2 cmul(float2 a, float2 b){
    return make_float2(fmaf(a.x, b.x, -a.y*b.y), fmaf(a.x, b.y, a.y*b.x));
}
__device__ __forceinline__ float2 rotn(float2 a){ return make_float2(a.y, -a.x); }
__device__ __forceinline__ float2 rotp(float2 a){ return make_float2(-a.y, a.x); }

__device__ __forceinline__ int dr10(int r){ int x = __brev((unsigned)r) >> 22; return ((x & 0x155) << 1) | ((x & 0x2AA) >> 1); }

// ---------------- zero accumulator ----------------
__global__ void k_zero_acc() {
    int i = blockIdx.x * blockDim.x + threadIdx.x;
    float4* p = (float4*)g_ACC;
    const int n = BATCH * NN * NN * 2 / 4;
    if (i < n) p[i] = make_float4(0.f, 0.f, 0.f, 0.f);
}

// ---------------- register DFT16 (Stockham radix-2, 4 stages, fully unrolled) ----------------
// SGN = +1 inverse, -1 forward. tw16[k] = exp(SGN*2*pi*i*k/16).
template<int SGN>
__device__ __forceinline__ void dft16(float2* r) {
    const float C1 = 0.923879532511287f, S1 = 0.382683432365090f, C2 = 0.707106781186548f;
    const float2 W[8] = {
        {1.f, 0.f}, {C1, SGN*S1}, {C2, SGN*C2}, {S1, SGN*C1},
        {0.f, SGN*1.f}, {-S1, SGN*C1}, {-C2, SGN*C2}, {-C1, SGN*S1}
    };
    float2 t[16];
    // stage 0: s=1, r -> t
    #pragma unroll
    for (int j = 0; j < 8; ++j) {
        float2 a = r[j], b = r[j+8];
        t[2*j]   = cadd(a, b);
        t[2*j+1] = cmul(csub(a, b), W[j]);
    }
    // stage 1: s=2, t -> r
    #pragma unroll
    for (int j = 0; j < 8; ++j) {
        int off = j & ~1;
        float2 a = t[j], b = t[j+8];
        r[j+off]   = cadd(a, b);
        r[j+off+2] = cmul(csub(a, b), W[off]);
    }
    // stage 2: s=4, r -> t
    #pragma unroll
    for (int j = 0; j < 8; ++j) {
        int off = j & ~3;
        float2 a = r[j], b = r[j+8];
        t[j+off]   = cadd(a, b);
        t[j+off+4] = cmul(csub(a, b), W[off]);
    }
    // stage 3: s=8, t -> r
    #pragma unroll
    for (int j = 0; j < 8; ++j) {
        float2 a = t[j], b = t[j+8];
        r[j]   = cadd(a, b);
        r[j+8] = cmul(csub(a, b), W[0]);   // off=0 -> w=1
    }
}

// ---------------- Stockham radix-4 for 1024 (kept from R4, verified) ----------------
template<int N, int NST, bool INV>
__device__ __forceinline__ float2* stockham_r4(float2* b0, float2* b1, const float2* tw, int j) {
    float2 *src = b0, *dst = b1;
    int s = 1;
    #pragma unroll
    for (int st = 0; st < NST; ++st) {
        int off = j & ~(s - 1);
        float2 x0 = src[j], x1 = src[j + N/4], x2 = src[j + N/2], x3 = src[j + 3*(N/4)];
        float2 w1 = tw[off], w2 = tw[2*off];
        float2 t0 = cadd(x0, x2), t1 = cmul(csub(x0, x2), w1);
        float2 t2 = cadd(x1, x3);
        float2 t3 = cmul(csub(x1, x3), w1);
        t3 = INV ? rotp(t3) : rotn(t3);
        float2 y0 = cadd(t0, t2), y1 = cadd(t1, t3);
        float2 y2 = cmul(csub(t0, t2), w2), y3 = cmul(csub(t1, t3), w2);
        if (st == 0) {
            float4* d4 = (float4*)(dst + 4*j);
            d4[0] = make_float4(y0.x, y0.y, y1.x, y1.y);
            d4[1] = make_float4(y2.x, y2.y, y3.x, y3.y);
        } else {
            int base = j + 3*off;
            dst[base]       = y0;
            dst[base + s]   = y1;
            dst[base + 2*s] = y2;
            dst[base + 3*s] = y3;
        }
        __syncthreads();
        float2* t = src; src = dst; dst = t;
        s <<= 2;
    }
    return src;
}

// ---------------- K1: forward row FFT1024 (2 rows/block) ----------------
__global__ void k_rows_fwd_planar(const float* __restrict__ re, const float* __restrict__ im) {
    __shared__ __align__(16) float2 buf[2][2][NN];
    __shared__ float2 tw[NN/2];
    int tid = threadIdx.x;
    int lrow = tid >> 8, j = tid & 255;
    #pragma unroll
    for (int h = 0; h < 2; ++h) {
        int i = tid + h * 512;
        float x = -2.0f * (float)i / (float)NN;
        float s, c; sincospif(x, &s, &c);
        if (i < NN/2) tw[i] = make_float2(c, s);
    }
    int row = blockIdx.x * 2 + lrow;
    const float* rp = re + (size_t)row * NN;
    const float* ip = im + (size_t)row * NN;
    float2* b0 = buf[lrow][0];
    float2* b1 = buf[lrow][1];
    #pragma unroll
    for (int h = 0; h < 4; ++h) b0[j + h*256] = make_float2(rp[j + h*256], ip[j + h*256]);
    __syncthreads();
    float2* res = stockham_r4<NN, 5, false>(b0, b1, tw, j);
    float2* o = g_X + (size_t)row * NN;
    #pragma unroll
    for (int h = 0; h < 4; ++h) o[j + h*256] = res[j + h*256];
}

// ---------------- K5: inverse row FFT1024 of ACC -> g_S1 ----------------
__global__ void k_rows_inv_acc() {
    __shared__ __align__(16) float2 buf[2][2][NN];
    __shared__ float2 tw[NN/2];
    int tid = threadIdx.x;
    int lrow = tid >> 8, j = tid & 255;
    #pragma unroll
    for (int h = 0; h < 2; ++h) {
        int i = tid + h * 512;
        float x = 2.0f * (float)i / (float)NN;
        float s, c; sincospif(x, &s, &c);
        if (i < NN/2) tw[i] = make_float2(c, s);
    }
    int row = blockIdx.x * 2 + lrow;
    const float2* src = ((const float2*)g_ACC) + (size_t)row * NN;
    float2* b0 = buf[lrow][0];
    float2* b1 = buf[lrow][1];
    #pragma unroll
    for (int h = 0; h < 4; ++h) b0[j + h*256] = src[j + h*256];
    __syncthreads();
    float2* res = stockham_r4<NN, 5, true>(b0, b1, tw, j);
    float2* o = g_S1 + (size_t)row * NN;
    #pragma unroll
    for (int h = 0; h < 4; ++h) o[j + h*256] = res[j + h*256];
}

// ---------------- column FFT 1024 (in-place radix-4 DIT, kept from R4) ----------------
#define CCOLS 8
#define CSTR  9
#define COL_SMEM_BYTES ((NN * CSTR + NN/2) * (int)sizeof(float2))

template<bool INV>
__device__ __forceinline__ void dit1024_ip(float2* sm, const float2* tw, int tid) {
    #pragma unroll
    for (int lg = 1; lg <= 5; ++lg) {
        const int q = (1 << (2*lg)) >> 2;
        #pragma unroll
        for (int u = 0; u < 4; ++u) {
            int t   = tid + (u << 9);
            int cc  = t & 7;
            int idx = t >> 3;
            int k   = idx & (q - 1);
            int g   = idx >> (2*lg - 2);
            int rb  = (g << (2*lg)) + k;
            int e   = k << (10 - 2*lg);
            float2 w1 = tw[e], w2 = tw[2*e];
            float2 w3 = cmul(w1, w2);
            float2 X0 = sm[rb*CSTR + cc];
            float2 X1 = cmul(sm[(rb+q)*CSTR + cc],   w1);
            float2 X2 = cmul(sm[(rb+2*q)*CSTR + cc], w2);
            float2 X3 = cmul(sm[(rb+3*q)*CSTR + cc], w3);
            float2 s  = cadd(X0, X2), d = csub(X0, X2);
            float2 s2 = cadd(X1, X3);
            float2 dd = csub(X1, X3);
            float2 d2 = INV ? rotp(dd) : rotn(dd);
            sm[rb*CSTR + cc]        = cadd(s, s2);
            sm[(rb+q)*CSTR + cc]    = cadd(d, d2);
            sm[(rb+2*q)*CSTR + cc]  = csub(s, s2);
            sm[(rb+3*q)*CSTR + cc]  = csub(d, d2);
        }
        __syncthreads();
    }
}

__global__ void k_cols_fwd_X() {
    extern __shared__ float2 smem[];
    float2* sm = smem;
    float2* tw = smem + NN * CSTR;
    int b  = blockIdx.x >> 7;
    int c0 = (blockIdx.x & 127) * CCOLS;
    int tid = threadIdx.x;
    {
        float x = -2.0f * (float)tid / (float)NN;
        float s, c; sincospif(x, &s, &c);
        tw[tid] = make_float2(c, s);
    }
    float2* img = g_X + (size_t)b * NN * NN;
    int c = tid & 7, r0 = tid >> 3;
    for (int it = 0; it < 16; ++it) {
        int r = r0 + (it << 6);
        sm[dr10(r) * CSTR + c] = img[(size_t)r * NN + c0 + c];
    }
    __syncthreads();
    dit1024_ip<false>(sm, tw, tid);
    for (int it = 0; it < 16; ++it) {
        int r = r0 + (it << 6);
        img[(size_t)r * NN + c0 + c] = sm[r * CSTR + c];
    }
}

__global__ void k_cols_inv_final(const float* __restrict__ img_a, const float* __restrict__ xre,
                                 const float* __restrict__ xim,  const float* __restrict__ lamb,
                                 const float* __restrict__ eta1, float* __restrict__ out,
                                 long long out_size) {
    extern __shared__ float2 smem[];
    float2* sm = smem;
    float2* tw = smem + NN * CSTR;
    int b  = blockIdx.x >> 7;
    int c0 = (blockIdx.x & 127) * CCOLS;
    int tid = threadIdx.x;
    {
        float x = 2.0f * (float)tid / (float)NN;
        float s, c; sincospif(x, &s, &c);
        tw[tid] = make_float2(c, s);
    }
    const float2* img = g_S1 + (size_t)b * NN * NN;
    int c = tid & 7, r0 = tid >> 3;
    for (int it = 0; it < 16; ++it) {
        int r = r0 + (it << 6);
        sm[dr10(r) * CSTR + c] = img[(size_t)r * NN + c0 + c];
    }
    __syncthreads();
    dit1024_ip<true>(sm, tw, tid);
    float e1  = eta1[0];
    float lm  = lamb[0];
    float bco = 100.0f * e1 * lm;
    float aco = 10.0f  * e1;
    float coef = aco / ((float)LL * 1048576.0f);
    float one_m_b = 1.0f - bco;
    for (int it = 0; it < 16; ++it) {
        int r = r0 + (it << 6);
        long long idx = ((long long)b * NN + r) * NN + c0 + c;
        float2 d = sm[r * CSTR + c];
        float xr = xre[idx], xi = xim[idx];
        float m  = sqrtf(fmaf(xr, xr, xi * xi)) + 1e-6f;
        float fa = bco * img_a[idx] / m;
        float rcx = one_m_b * xr - coef * d.x + fa * xr;
        float rcy = one_m_b * xi - coef * d.y + fa * xi;
        if (idx < out_size) out[idx] = sqrtf(fmaf(rcx, rcx, rcy * rcy));
        long long ore = (long long)IMG_PIX + idx;
        long long oim = (long long)(2 * IMG_PIX) + idx;
        if (ore < out_size) out[ore] = rcx;
        if (oim < out_size) out[oim] = rcy;
    }
}

// ================= patch kernels: four-step 16x16 register FFT =================

// ---------------- P1: gather*CTF + row IFFT256 -> g_S1 ----------------
// block = 256 thr = 16 rows x 16 threads; grid = B*L*16
__global__ __launch_bounds__(256) void k_p1(const int* __restrict__ masks, const float* __restrict__ ctf) {
    __shared__ float2 S[16 * 272];             // [r][k1*17 + t]
    int tid = threadIdx.x;
    int r = tid >> 4, t = tid & 15;
    int rg = blockIdx.x & 15;
    int pk = blockIdx.x >> 4;
    int b  = pk >> 6, k = pk & 63;
    int mr = masks[2*k] - 1, mc = masks[2*k+1] - 1;
    int i  = (rg << 4) + r;                    // patch row
    int gr = (mr + i + 512) & 1023;
    const float2* Xrow = g_X + ((size_t)b * NN + gr) * NN;
    const float*  cfr  = ctf + i * NP;
    float2 x[16];
    #pragma unroll
    for (int m = 0; m < 16; ++m) {
        int j  = m*16 + t;
        int gc = (mc + j + 512) & 1023;
        float2 v = Xrow[gc];
        float cf = cfr[j];
        x[m] = make_float2(v.x * cf, v.y * cf);
    }
    dft16<+1>(x);
    float ss, cc; sincospif(2.0f * (float)t / 256.0f, &ss, &cc);
    float2 wt = make_float2(cc, ss);
    float2 w  = make_float2(1.f, 0.f);
    float2* Sr = S + r * 272;
    #pragma unroll
    for (int k1 = 0; k1 < 16; ++k1) {
        Sr[k1*17 + t] = cmul(x[k1], w);
        w = cmul(w, wt);
    }
    __syncthreads();
    float2 y[16];
    #pragma unroll
    for (int n2 = 0; n2 < 16; ++n2) y[n2] = Sr[t*17 + n2];
    dft16<+1>(y);
    float2* o = g_S1 + ((size_t)pk * NP + i) * NP;
    #pragma unroll
    for (int k2 = 0; k2 < 16; ++k2) o[t + 16*k2] = y[k2];
}

// ---------------- P2: col IFFT256 + projection + col FFT256 ----------------
// block = 256 thr = 16 t x 16 cols; grid = B*L*16 (16-col tiles)
__global__ __launch_bounds__(256) void k_p2(const float* __restrict__ Y) {
    __shared__ float2 S[16 * 256];             // [k1][t][c]: strides 256,16,1
    int tid = threadIdx.x;
    int t = tid >> 4, c = tid & 15;
    int pk = blockIdx.x >> 4;
    int c0 = (blockIdx.x & 15) << 4;
    float2* P = g_S1 + (size_t)pk * NP * NP;
    float2 x[16];
    #pragma unroll
    for (int m = 0; m < 16; ++m) x[m] = P[(m*16 + t) * NP + c0 + c];
    dft16<+1>(x);
    {
        float ss, cc; sincospif(2.0f * (float)t / 256.0f, &ss, &cc);
        float2 wt = make_float2(cc, ss);
        float2 w  = make_float2(1.f, 0.f);
        #pragma unroll
        for (int k1 = 0; k1 < 16; ++k1) {
            S[k1*256 + t*16 + c] = cmul(x[k1], w);
            w = cmul(w, wt);
        }
    }
    __syncthreads();
    float2 y[16];
    #pragma unroll
    for (int n2 = 0; n2 < 16; ++n2) y[n2] = S[t*256 + n2*16 + c];
    dft16<+1>(y);
    // projection; thread t holds rows (t + 16*k2)
    const float* Yp = Y + (size_t)pk * NP * NP;
    const float inv = 1.0f / 65536.0f;
    #pragma unroll
    for (int k2 = 0; k2 < 16; ++k2) {
        float2 wv = make_float2(y[k2].x * inv, y[k2].y * inv);
        float mag = sqrtf(fmaf(wv.x, wv.x, wv.y * wv.y));
        float sy  = sqrtf(Yp[(t + 16*k2) * NP + c0 + c]);
        if (mag > 0.0f) {
            float f = 1.0f - sy / mag;
            y[k2] = make_float2(wv.x * f, wv.y * f);
        } else {
            y[k2] = make_float2(-sy, 0.0f);
        }
    }
    // forward col FFT: rows = 16*m + t with m = reg index
    dft16<-1>(y);
    __syncthreads();                           // before reusing S
    {
        float ss, cc; sincospif(-2.0f * (float)t / 256.0f, &ss, &cc);
        float2 wt = make_float2(cc, ss);
        float2 w  = make_float2(1.f, 0.f);
        #pragma unroll
        for (int k1 = 0; k1 < 16; ++k1) {
            S[k1*256 + t*16 + c] = cmul(y[k1], w);
            w = cmul(w, wt);
        }
    }
    __syncthreads();
    float2 z[16];
    #pragma unroll
    for (int n2 = 0; n2 < 16; ++n2) z[n2] = S[t*256 + n2*16 + c];
    dft16<-1>(z);
    #pragma unroll
    for (int k2 = 0; k2 < 16; ++k2) P[(t + 16*k2) * NP + c0 + c] = z[k2];
}

// ---------------- P3: row FFT256 * CTF + atomic scatter ----------------
__global__ __launch_bounds__(256) void k_p3(const int* __restrict__ masks, const float* __restrict__ ctf) {
    __shared__ float2 S[16 * 272];
    int tid = threadIdx.x;
    int r = tid >> 4, t = tid & 15;
    int rg = blockIdx.x & 15;
    int pk = blockIdx.x >> 4;
    int b  = pk >> 6, k = pk & 63;
    int mr = masks[2*k] - 1, mc = masks[2*k+1] - 1;
    int i  = (rg << 4) + r;
    const float2* src = g_S1 + ((size_t)pk * NP + i) * NP;
    float2 x[16];
    #pragma unroll
    for (int m = 0; m < 16; ++m) x[m] = src[m*16 + t];
    dft16<-1>(x);
    float ss, cc; sincospif(-2.0f * (float)t / 256.0f, &ss, &cc);
    float2 wt = make_float2(cc, ss);
    float2 w  = make_float2(1.f, 0.f);
    float2* Sr = S + r * 272;
    #pragma unroll
    for (int k1 = 0; k1 < 16; ++k1) {
        Sr[k1*17 + t] = cmul(x[k1], w);
        w = cmul(w, wt);
    }
    __syncthreads();
    float2 y[16];
    #pragma unroll
    for (int n2 = 0; n2 < 16; ++n2) y[n2] = Sr[t*17 + n2];
    dft16<-1>(y);
    int gr = (mr + i + 512) & 1023;
    float* accrow = g_ACC + ((size_t)b * NN + gr) * NN * 2;
    const float* cfr = ctf + i * NP;
    #pragma unroll
    for (int k2 = 0; k2 < 16; ++k2) {
        int j  = t + 16*k2;
        float cf = cfr[j];
        int gc = (mc + j + 512) & 1023;
        atomicAdd(accrow + gc*2,     y[k2].x * cf);
        atomicAdd(accrow + gc*2 + 1, y[k2].y * cf);
    }
}

// ---------------- launch ----------------
extern "C" void kernel_launch(void* const* d_in, const int* in_sizes, int n_in,
                              void* d_out, int out_size) {
    const float* Img_a = (const float*)d_in[0];
    const float* Xre   = (const float*)d_in[1];
    const float* Xim   = (const float*)d_in[2];
    const float* Y     = (const float*)d_in[3];
    const int*   Masks = (const int*)  d_in[4];
    const float* CTF   = (const float*)d_in[5];
    const float* lamb  = (const float*)d_in[6];
    const float* eta1  = (const float*)d_in[7];
    float* out = (float*)d_out;

    cudaFuncSetAttribute((const void*)k_cols_fwd_X,
                         cudaFuncAttributeMaxDynamicSharedMemorySize, COL_SMEM_BYTES);
    cudaFuncSetAttribute((const void*)k_cols_inv_final,
                         cudaFuncAttributeMaxDynamicSharedMemorySize, COL_SMEM_BYTES);

    k_zero_acc<<<4096, 512>>>();
    k_rows_fwd_planar<<<BATCH * NN / 2, 512>>>(Xre, Xim);
    k_cols_fwd_X<<<BATCH * (NN / CCOLS), 512, COL_SMEM_BYTES>>>();
    k_p1<<<BATCH * LL * 16, 256>>>(Masks, CTF);
    k_p2<<<BATCH * LL * 16, 256>>>(Y);
    k_p3<<<BATCH * LL * 16, 256>>>(Masks, CTF);
    k_rows_inv_acc<<<BATCH * NN / 2, 512>>>();
    k_cols_inv_final<<<BATCH * (NN / CCOLS), 512, COL_SMEM_BYTES>>>(
        Img_a, Xre, Xim, lamb, eta1, out, (long long)out_size);
}

// round 6
// speedup vs baseline: 2.0914x; 1.0484x over previous
#include <cuda_runtime.h>
#include <cstdint>

#define BATCH 4
#define NN 1024
#define LL 64
#define NP 256
#define IMG_PIX (BATCH * NN * NN)

// ---------------- scratch ----------------
__device__ float2 g_X[BATCH * NN * NN];
__device__ float2 g_S1[BATCH * LL * NP * NP];
__device__ float  g_ACC[BATCH * NN * NN * 2];

// ---------------- complex helpers ----------------
__device__ __forceinline__ float2 cadd(float2 a, float2 b){ return make_float2(a.x+b.x, a.y+b.y); }
__device__ __forceinline__ float2 csub(float2 a, float2 b){ return make_float2(a.x-b.x, a.y-b.y); }
__device__ __forceinline__ float2 cmul(float2 a, float2 b){
    return make_float2(fmaf(a.x, b.x, -a.y*b.y), fmaf(a.x, b.y, a.y*b.x));
}

// ---------------- zero accumulator ----------------
__global__ void k_zero_acc() {
    int i = blockIdx.x * blockDim.x + threadIdx.x;
    float4* p = (float4*)g_ACC;
    const int n = BATCH * NN * NN * 2 / 4;
    if (i < n) p[i] = make_float4(0.f, 0.f, 0.f, 0.f);
}

// ---------------- register DFT16 (Stockham radix-2, verified R5) ----------------
template<int SGN>
__device__ __forceinline__ void dft16(float2* r) {
    const float C1 = 0.923879532511287f, S1 = 0.382683432365090f, C2 = 0.707106781186548f;
    const float2 W[8] = {
        {1.f, 0.f}, {C1, SGN*S1}, {C2, SGN*C2}, {S1, SGN*C1},
        {0.f, SGN*1.f}, {-S1, SGN*C1}, {-C2, SGN*C2}, {-C1, SGN*S1}
    };
    float2 t[16];
    #pragma unroll
    for (int j = 0; j < 8; ++j) {
        float2 a = r[j], b = r[j+8];
        t[2*j]   = cadd(a, b);
        t[2*j+1] = cmul(csub(a, b), W[j]);
    }
    #pragma unroll
    for (int j = 0; j < 8; ++j) {
        int off = j & ~1;
        float2 a = t[j], b = t[j+8];
        r[j+off]   = cadd(a, b);
        r[j+off+2] = cmul(csub(a, b), W[off]);
    }
    #pragma unroll
    for (int j = 0; j < 8; ++j) {
        int off = j & ~3;
        float2 a = r[j], b = r[j+8];
        t[j+off]   = cadd(a, b);
        t[j+off+4] = cmul(csub(a, b), W[off]);
    }
    #pragma unroll
    for (int j = 0; j < 8; ++j) {
        float2 a = t[j], b = t[j+8];
        r[j]   = cadd(a, b);
        r[j+8] = csub(a, b);
    }
}

// ---------------- register DFT32 (Stockham radix-2, 5 stages) ----------------
template<int SGN>
__device__ __forceinline__ void dft32(float2* r) {
    const float A1 = 0.980785280403230f, B1 = 0.195090322016128f;
    const float A2 = 0.923879532511287f, B2 = 0.382683432365090f;
    const float A3 = 0.831469612302545f, B3 = 0.555570233019602f;
    const float A4 = 0.707106781186548f;
    const float2 W[16] = {
        {1.f, 0.f},      {A1, SGN*B1},   {A2, SGN*B2},   {A3, SGN*B3},
        {A4, SGN*A4},    {B3, SGN*A3},   {B2, SGN*A2},   {B1, SGN*A1},
        {0.f, SGN*1.f},  {-B1, SGN*A1},  {-B2, SGN*A2},  {-B3, SGN*A3},
        {-A4, SGN*A4},   {-A3, SGN*B3},  {-A2, SGN*B2},  {-A1, SGN*B1}
    };
    float2 t[32];
    #pragma unroll
    for (int j = 0; j < 16; ++j) {           // s=1, r->t
        float2 a = r[j], b = r[j+16];
        t[2*j]   = cadd(a, b);
        t[2*j+1] = cmul(csub(a, b), W[j]);
    }
    #pragma unroll
    for (int j = 0; j < 16; ++j) {           // s=2, t->r
        int off = j & ~1;
        float2 a = t[j], b = t[j+16];
        r[j+off]   = cadd(a, b);
        r[j+off+2] = cmul(csub(a, b), W[off]);
    }
    #pragma unroll
    for (int j = 0; j < 16; ++j) {           // s=4, r->t
        int off = j & ~3;
        float2 a = r[j], b = r[j+16];
        t[j+off]   = cadd(a, b);
        t[j+off+4] = cmul(csub(a, b), W[off]);
    }
    #pragma unroll
    for (int j = 0; j < 16; ++j) {           // s=8, t->r
        int off = j & ~7;
        float2 a = t[j], b = t[j+16];
        r[j+off]   = cadd(a, b);
        r[j+off+8] = cmul(csub(a, b), W[off]);
    }
    #pragma unroll
    for (int j = 0; j < 16; ++j) {           // s=16, r->t (off=0, w=1)
        float2 a = r[j], b = r[j+16];
        t[j]    = cadd(a, b);
        t[j+16] = csub(a, b);
    }
    #pragma unroll
    for (int j = 0; j < 32; ++j) r[j] = t[j];
}

// ================= 1024-pt kernels: four-step 32x32 register FFT =================
// Row kernels: 128 thr = 4 rows x 32 threads. One smem crossing, padded 33.

// ---------------- K1: forward row FFT1024 of planar input -> g_X ----------------
__global__ __launch_bounds__(128) void k_rows_fwd_planar(const float* __restrict__ re, const float* __restrict__ im) {
    __shared__ float2 S[4 * 1056];             // [r][k1*33 + t]
    int tid = threadIdx.x;
    int r = tid >> 5, t = tid & 31;
    int row = blockIdx.x * 4 + r;
    const float* rp = re + (size_t)row * NN;
    const float* ip = im + (size_t)row * NN;
    float2 x[32];
    #pragma unroll
    for (int m = 0; m < 32; ++m) x[m] = make_float2(rp[m*32 + t], ip[m*32 + t]);
    dft32<-1>(x);
    float ss, cc; sincospif(-(float)t / 512.0f, &ss, &cc);   // exp(-2pi i t/1024)
    float2 wt = make_float2(cc, ss);
    float2 w  = make_float2(1.f, 0.f);
    float2* Sr = S + r * 1056;
    #pragma unroll
    for (int k1 = 0; k1 < 32; ++k1) {
        Sr[k1*33 + t] = cmul(x[k1], w);
        w = cmul(w, wt);
    }
    __syncthreads();
    float2 y[32];
    #pragma unroll
    for (int n2 = 0; n2 < 32; ++n2) y[n2] = Sr[t*33 + n2];
    dft32<-1>(y);
    float2* o = g_X + (size_t)row * NN;
    #pragma unroll
    for (int k2 = 0; k2 < 32; ++k2) o[t + 32*k2] = y[k2];
}

// ---------------- K5: inverse row FFT1024 of ACC -> g_S1 ----------------
__global__ __launch_bounds__(128) void k_rows_inv_acc() {
    __shared__ float2 S[4 * 1056];
    int tid = threadIdx.x;
    int r = tid >> 5, t = tid & 31;
    int row = blockIdx.x * 4 + r;
    const float2* src = ((const float2*)g_ACC) + (size_t)row * NN;
    float2 x[32];
    #pragma unroll
    for (int m = 0; m < 32; ++m) x[m] = src[m*32 + t];
    dft32<+1>(x);
    float ss, cc; sincospif((float)t / 512.0f, &ss, &cc);
    float2 wt = make_float2(cc, ss);
    float2 w  = make_float2(1.f, 0.f);
    float2* Sr = S + r * 1056;
    #pragma unroll
    for (int k1 = 0; k1 < 32; ++k1) {
        Sr[k1*33 + t] = cmul(x[k1], w);
        w = cmul(w, wt);
    }
    __syncthreads();
    float2 y[32];
    #pragma unroll
    for (int n2 = 0; n2 < 32; ++n2) y[n2] = Sr[t*33 + n2];
    dft32<+1>(y);
    float2* o = g_S1 + (size_t)row * NN;
    #pragma unroll
    for (int k2 = 0; k2 < 32; ++k2) o[t + 32*k2] = y[k2];
}

// Col kernels: 256 thr = 8 cols, tid = t*8 + c; per-col smem stride 1058 (bank-tuned).
#define COLS_SMEM_BYTES (8 * 1058 * (int)sizeof(float2))   // 67,712

__global__ __launch_bounds__(256) void k_cols_fwd_X() {
    extern __shared__ float2 S[];
    int tid = threadIdx.x;
    int c = tid & 7, t = tid >> 3;
    int b  = blockIdx.x >> 7;
    int c0 = (blockIdx.x & 127) * 8;
    float2* img = g_X + (size_t)b * NN * NN;
    float2 x[32];
    #pragma unroll
    for (int m = 0; m < 32; ++m) x[m] = img[(size_t)(m*32 + t) * NN + c0 + c];
    dft32<-1>(x);
    float ss, cc; sincospif(-(float)t / 512.0f, &ss, &cc);
    float2 wt = make_float2(cc, ss);
    float2 w  = make_float2(1.f, 0.f);
    float2* Sc = S + c * 1058;
    #pragma unroll
    for (int k1 = 0; k1 < 32; ++k1) {
        Sc[k1*33 + t] = cmul(x[k1], w);
        w = cmul(w, wt);
    }
    __syncthreads();
    float2 y[32];
    #pragma unroll
    for (int n2 = 0; n2 < 32; ++n2) y[n2] = Sc[t*33 + n2];
    dft32<-1>(y);
    #pragma unroll
    for (int k2 = 0; k2 < 32; ++k2) img[(size_t)(t + 32*k2) * NN + c0 + c] = y[k2];
}

__global__ __launch_bounds__(256) void k_cols_inv_final(const float* __restrict__ img_a, const float* __restrict__ xre,
                                 const float* __restrict__ xim,  const float* __restrict__ lamb,
                                 const float* __restrict__ eta1, float* __restrict__ out,
                                 long long out_size) {
    extern __shared__ float2 S[];
    int tid = threadIdx.x;
    int c = tid & 7, t = tid >> 3;
    int b  = blockIdx.x >> 7;
    int c0 = (blockIdx.x & 127) * 8;
    const float2* img = g_S1 + (size_t)b * NN * NN;
    float2 x[32];
    #pragma unroll
    for (int m = 0; m < 32; ++m) x[m] = img[(size_t)(m*32 + t) * NN + c0 + c];
    dft32<+1>(x);
    float ss, cc; sincospif((float)t / 512.0f, &ss, &cc);
    float2 wt = make_float2(cc, ss);
    float2 w  = make_float2(1.f, 0.f);
    float2* Sc = S + c * 1058;
    #pragma unroll
    for (int k1 = 0; k1 < 32; ++k1) {
        Sc[k1*33 + t] = cmul(x[k1], w);
        w = cmul(w, wt);
    }
    __syncthreads();
    float2 y[32];
    #pragma unroll
    for (int n2 = 0; n2 < 32; ++n2) y[n2] = Sc[t*33 + n2];
    dft32<+1>(y);
    float e1  = eta1[0];
    float lm  = lamb[0];
    float bco = 100.0f * e1 * lm;
    float aco = 10.0f  * e1;
    float coef = aco / ((float)LL * 1048576.0f);
    float one_m_b = 1.0f - bco;
    #pragma unroll
    for (int k2 = 0; k2 < 32; ++k2) {
        int rrow = t + 32*k2;
        long long idx = ((long long)b * NN + rrow) * NN + c0 + c;
        float2 d = y[k2];
        float xr = xre[idx], xi = xim[idx];
        float m  = sqrtf(fmaf(xr, xr, xi * xi)) + 1e-6f;
        float fa = bco * img_a[idx] / m;
        float rcx = one_m_b * xr - coef * d.x + fa * xr;
        float rcy = one_m_b * xi - coef * d.y + fa * xi;
        if (idx < out_size) out[idx] = sqrtf(fmaf(rcx, rcx, rcy * rcy));
        long long ore = (long long)IMG_PIX + idx;
        long long oim = (long long)(2 * IMG_PIX) + idx;
        if (ore < out_size) out[ore] = rcx;
        if (oim < out_size) out[oim] = rcy;
    }
}

// ================= patch kernels (verified R5, untouched) =================

__global__ __launch_bounds__(256) void k_p1(const int* __restrict__ masks, const float* __restrict__ ctf) {
    __shared__ float2 S[16 * 272];
    int tid = threadIdx.x;
    int r = tid >> 4, t = tid & 15;
    int rg = blockIdx.x & 15;
    int pk = blockIdx.x >> 4;
    int b  = pk >> 6, k = pk & 63;
    int mr = masks[2*k] - 1, mc = masks[2*k+1] - 1;
    int i  = (rg << 4) + r;
    int gr = (mr + i + 512) & 1023;
    const float2* Xrow = g_X + ((size_t)b * NN + gr) * NN;
    const float*  cfr  = ctf + i * NP;
    float2 x[16];
    #pragma unroll
    for (int m = 0; m < 16; ++m) {
        int j  = m*16 + t;
        int gc = (mc + j + 512) & 1023;
        float2 v = Xrow[gc];
        float cf = cfr[j];
        x[m] = make_float2(v.x * cf, v.y * cf);
    }
    dft16<+1>(x);
    float ss, cc; sincospif(2.0f * (float)t / 256.0f, &ss, &cc);
    float2 wt = make_float2(cc, ss);
    float2 w  = make_float2(1.f, 0.f);
    float2* Sr = S + r * 272;
    #pragma unroll
    for (int k1 = 0; k1 < 16; ++k1) {
        Sr[k1*17 + t] = cmul(x[k1], w);
        w = cmul(w, wt);
    }
    __syncthreads();
    float2 y[16];
    #pragma unroll
    for (int n2 = 0; n2 < 16; ++n2) y[n2] = Sr[t*17 + n2];
    dft16<+1>(y);
    float2* o = g_S1 + ((size_t)pk * NP + i) * NP;
    #pragma unroll
    for (int k2 = 0; k2 < 16; ++k2) o[t + 16*k2] = y[k2];
}

__global__ __launch_bounds__(256) void k_p2(const float* __restrict__ Y) {
    __shared__ float2 S[16 * 256];
    int tid = threadIdx.x;
    int t = tid >> 4, c = tid & 15;
    int pk = blockIdx.x >> 4;
    int c0 = (blockIdx.x & 15) << 4;
    float2* P = g_S1 + (size_t)pk * NP * NP;
    float2 x[16];
    #pragma unroll
    for (int m = 0; m < 16; ++m) x[m] = P[(m*16 + t) * NP + c0 + c];
    dft16<+1>(x);
    {
        float ss, cc; sincospif(2.0f * (float)t / 256.0f, &ss, &cc);
        float2 wt = make_float2(cc, ss);
        float2 w  = make_float2(1.f, 0.f);
        #pragma unroll
        for (int k1 = 0; k1 < 16; ++k1) {
            S[k1*256 + t*16 + c] = cmul(x[k1], w);
            w = cmul(w, wt);
        }
    }
    __syncthreads();
    float2 y[16];
    #pragma unroll
    for (int n2 = 0; n2 < 16; ++n2) y[n2] = S[t*256 + n2*16 + c];
    dft16<+1>(y);
    const float* Yp = Y + (size_t)pk * NP * NP;
    const float inv = 1.0f / 65536.0f;
    #pragma unroll
    for (int k2 = 0; k2 < 16; ++k2) {
        float2 wv = make_float2(y[k2].x * inv, y[k2].y * inv);
        float mag = sqrtf(fmaf(wv.x, wv.x, wv.y * wv.y));
        float sy  = sqrtf(Yp[(t + 16*k2) * NP + c0 + c]);
        if (mag > 0.0f) {
            float f = 1.0f - sy / mag;
            y[k2] = make_float2(wv.x * f, wv.y * f);
        } else {
            y[k2] = make_float2(-sy, 0.0f);
        }
    }
    dft16<-1>(y);
    __syncthreads();
    {
        float ss, cc; sincospif(-2.0f * (float)t / 256.0f, &ss, &cc);
        float2 wt = make_float2(cc, ss);
        float2 w  = make_float2(1.f, 0.f);
        #pragma unroll
        for (int k1 = 0; k1 < 16; ++k1) {
            S[k1*256 + t*16 + c] = cmul(y[k1], w);
            w = cmul(w, wt);
        }
    }
    __syncthreads();
    float2 z[16];
    #pragma unroll
    for (int n2 = 0; n2 < 16; ++n2) z[n2] = S[t*256 + n2*16 + c];
    dft16<-1>(z);
    #pragma unroll
    for (int k2 = 0; k2 < 16; ++k2) P[(t + 16*k2) * NP + c0 + c] = z[k2];
}

__global__ __launch_bounds__(256) void k_p3(const int* __restrict__ masks, const float* __restrict__ ctf) {
    __shared__ float2 S[16 * 272];
    int tid = threadIdx.x;
    int r = tid >> 4, t = tid & 15;
    int rg = blockIdx.x & 15;
    int pk = blockIdx.x >> 4;
    int b  = pk >> 6, k = pk & 63;
    int mr = masks[2*k] - 1, mc = masks[2*k+1] - 1;
    int i  = (rg << 4) + r;
    const float2* src = g_S1 + ((size_t)pk * NP + i) * NP;
    float2 x[16];
    #pragma unroll
    for (int m = 0; m < 16; ++m) x[m] = src[m*16 + t];
    dft16<-1>(x);
    float ss, cc; sincospif(-2.0f * (float)t / 256.0f, &ss, &cc);
    float2 wt = make_float2(cc, ss);
    float2 w  = make_float2(1.f, 0.f);
    float2* Sr = S + r * 272;
    #pragma unroll
    for (int k1 = 0; k1 < 16; ++k1) {
        Sr[k1*17 + t] = cmul(x[k1], w);
        w = cmul(w, wt);
    }
    __syncthreads();
    float2 y[16];
    #pragma unroll
    for (int n2 = 0; n2 < 16; ++n2) y[n2] = Sr[t*17 + n2];
    dft16<-1>(y);
    int gr = (mr + i + 512) & 1023;
    float* accrow = g_ACC + ((size_t)b * NN + gr) * NN * 2;
    const float* cfr = ctf + i * NP;
    #pragma unroll
    for (int k2 = 0; k2 < 16; ++k2) {
        int j  = t + 16*k2;
        float cf = cfr[j];
        int gc = (mc + j + 512) & 1023;
        atomicAdd(accrow + gc*2,     y[k2].x * cf);
        atomicAdd(accrow + gc*2 + 1, y[k2].y * cf);
    }
}

// ---------------- launch ----------------
extern "C" void kernel_launch(void* const* d_in, const int* in_sizes, int n_in,
                              void* d_out, int out_size) {
    const float* Img_a = (const float*)d_in[0];
    const float* Xre   = (const float*)d_in[1];
    const float* Xim   = (const float*)d_in[2];
    const float* Y     = (const float*)d_in[3];
    const int*   Masks = (const int*)  d_in[4];
    const float* CTF   = (const float*)d_in[5];
    const float* lamb  = (const float*)d_in[6];
    const float* eta1  = (const float*)d_in[7];
    float* out = (float*)d_out;

    cudaFuncSetAttribute((const void*)k_cols_fwd_X,
                         cudaFuncAttributeMaxDynamicSharedMemorySize, COLS_SMEM_BYTES);
    cudaFuncSetAttribute((const void*)k_cols_inv_final,
                         cudaFuncAttributeMaxDynamicSharedMemorySize, COLS_SMEM_BYTES);

    k_zero_acc<<<4096, 512>>>();
    k_rows_fwd_planar<<<BATCH * NN / 4, 128>>>(Xre, Xim);
    k_cols_fwd_X<<<BATCH * 128, 256, COLS_SMEM_BYTES>>>();
    k_p1<<<BATCH * LL * 16, 256>>>(Masks, CTF);
    k_p2<<<BATCH * LL * 16, 256>>>(Y);
    k_p3<<<BATCH * LL * 16, 256>>>(Masks, CTF);
    k_rows_inv_acc<<<BATCH * NN / 4, 128>>>();
    k_cols_inv_final<<<BATCH * 128, 256, COLS_SMEM_BYTES>>>(
        Img_a, Xre, Xim, lamb, eta1, out, (long long)out_size);
}